// round 11
// baseline (speedup 1.0000x reference)
#include <cuda_runtime.h>

// BidirectionalLSTMComplex: S=1024, B=2048, H=32, IN=1, OUT=1
// Round 11: round-10 structure + (a) c-states in registers (fixed finalize
// role per thread), (b) gate pairs stored as float2 (STS.64/LDS.64).

#define S_LEN 1024
#define B_TOT 2048
#define HID   32
#define GATES 128
#define NB    7
#define NCTA  296
#define HP    36

typedef unsigned long long u64;

__device__ __forceinline__ void fma2(u64 &acc, u64 a, u64 b) {
    asm("fma.rn.f32x2 %0, %1, %2, %3;" : "=l"(acc) : "l"(a), "l"(b), "l"(acc));
}
__device__ __forceinline__ void add2(u64 &a, u64 b) {
    asm("add.rn.f32x2 %0, %1, %2;" : "=l"(a) : "l"(a), "l"(b));
}
__device__ __forceinline__ float hsum2(u64 v) {
    float lo, hi;
    asm("mov.b64 {%0,%1}, %2;" : "=f"(lo), "=f"(hi) : "l"(v));
    return lo + hi;
}
__device__ __forceinline__ float tanh_fast(float x) {
    float y;
    asm("tanh.approx.f32 %0, %1;" : "=f"(y) : "f"(x));
    return y;
}
__device__ __forceinline__ float sigm(float x) {
    return fmaf(tanh_fast(x * 0.5f), 0.5f, 0.5f);
}

__device__ __forceinline__ void load_row(u64 *w, const float *base) {
    const ulonglong2 *p = (const ulonglong2 *)base;
#pragma unroll
    for (int i = 0; i < 8; i++) {
        ulonglong2 q = p[i];
        w[2 * i]     = q.x;
        w[2 * i + 1] = q.y;
    }
}

// paired finalize: .x-cell (c0,h0) and .y-cell (c1,h1), MUFUs interleaved
__device__ __forceinline__ void cell_pair(const float2 *g, float &c0, float &c1,
                                          float *h0, float *h1, int m) {
    float2 gi = g[m], gf = g[m + 32], gg = g[m + 64], go = g[m + 96];
    float sfa = sigm(gf.x), sfb = sigm(gf.y);
    float sia = sigm(gi.x), sib = sigm(gi.y);
    float tga = tanh_fast(gg.x), tgb = tanh_fast(gg.y);
    float soa = sigm(go.x), sob = sigm(go.y);
    float c2a = sfa * c0 + sia * tga;
    float c2b = sfb * c1 + sib * tgb;
    c0 = c2a; c1 = c2b;
    h0[m] = soa * tanh_fast(c2a);
    h1[m] = sob * tanh_fast(c2b);
}

__device__ __forceinline__ void cell_x(const float2 *g, float &c, float *h, int m) {
    float gi = g[m].x, gf = g[m + 32].x, gg = g[m + 64].x, go = g[m + 96].x;
    float c2 = sigm(gf) * c + sigm(gi) * tanh_fast(gg);
    c = c2;
    h[m] = sigm(go) * tanh_fast(c2);
}
__device__ __forceinline__ void cell_y(const float2 *g, float &c, float *h, int m) {
    float gi = g[m].y, gf = g[m + 32].y, gg = g[m + 64].y, go = g[m + 96].y;
    float c2 = sigm(gf) * c + sigm(gi) * tanh_fast(gg);
    c = c2;
    h[m] = sigm(go) * tanh_fast(c2);
}

__global__ void __launch_bounds__(256, 2)
lstm_kernel(const float *__restrict__ x,
            const float *__restrict__ Wih_f0, const float *__restrict__ Whh_f0, const float *__restrict__ b_f0,
            const float *__restrict__ Wih_f1, const float *__restrict__ Whh_f1, const float *__restrict__ b_f1,
            const float *__restrict__ Wih_b0, const float *__restrict__ Whh_b0, const float *__restrict__ b_b0,
            const float *__restrict__ Wih_b1, const float *__restrict__ Whh_b1, const float *__restrict__ b_b1,
            const float *__restrict__ Wlin,   const float *__restrict__ blin,
            const int *__restrict__ future_p,
            float *__restrict__ out)
{
    const int tid  = threadIdx.x;
    const int j    = tid & 127;
    const bool isF = tid < 128;
    const int nb0  = blockIdx.x * NB;

    __shared__ __align__(16) float hf0s[NB][HP];
    __shared__ __align__(16) float hf1s[2][NB][HP];
    __shared__ __align__(16) float hb0s[NB][HP];
    __shared__ __align__(16) float hb1s[2][NB][HP];
    __shared__ __align__(16) float2 gF[NB][GATES];   // (f0gate, f1gate)
    __shared__ __align__(16) float2 gB[NB][GATES];   // (b0gate, b1gate)
    __shared__ float xs[NB], xbs[NB];
    __shared__ __align__(16) float wls[2 * HID];
    __shared__ float blin_s;

    u64 w0[16], w1[16], w2[16];
    float bias0, bias1, wx;
    if (isF) {
        load_row(w0, Whh_f0 + j * HID);
        load_row(w1, Wih_f1 + j * HID);
        load_row(w2, Whh_f1 + j * HID);
        bias0 = b_f0[j]; bias1 = b_f1[j]; wx = Wih_f0[j];
    } else {
        load_row(w0, Whh_b0 + j * HID);
        load_row(w1, Wih_b1 + j * HID);
        load_row(w2, Whh_b1 + j * HID);   // on hf1 (replicated bug)
        bias0 = b_b0[j]; bias1 = b_b1[j]; wx = Wih_b0[j];
    }
    const int fut = future_p[0];
    const float *xbase = x + nb0;
    const bool jval = (j < NB) && (nb0 + j < B_TOT);

    // per-thread c-states (layer0 a/b = n=ng, ng+4; layer1 a/b)
    float c0_a = 0.f, c0_b = 0.f, c1_a = 0.f, c1_b = 0.f;

    for (int i = tid; i < NB * HP; i += 256) {
        ((float *)hf0s)[i] = 0.f; ((float *)hb0s)[i] = 0.f;
    }
    for (int i = tid; i < 2 * NB * HP; i += 256) {
        ((float *)hf1s)[i] = 0.f; ((float *)hb1s)[i] = 0.f;
    }
    if (tid < 2 * HID) wls[tid] = Wlin[tid];
    if (tid == 0) blin_s = blin[0];

    int rb = fut % S_LEN; if (rb < 0) rb += S_LEN;     // backward index for t=0

    if (tid < NB) {
        xs[tid] = jval ? xbase[tid] : 0.f;
    } else if (tid >= 128 && tid < 128 + NB) {
        xbs[tid - 128] = jval ? xbase[rb * B_TOT + (tid - 128)] : 0.f;
    }
    rb--; if (rb < 0) rb += S_LEN;                     // index for t=1

    __syncthreads();

    const int m  = j & 31;
    const int ng = j >> 5;

    // prologue: f0_0 from zero state (only .x of gF used)
    if (isF) {
#pragma unroll
        for (int n = 0; n < NB; n++) gF[n][j].x = bias0 + wx * xs[n];
    }
    __syncthreads();
    if (isF) {
        if (ng < 3) {
            cell_x(gF[ng],     c0_a, hf0s[ng],     m);
            cell_x(gF[ng + 4], c0_b, hf0s[ng + 4], m);
        } else {
            cell_x(gF[3], c0_a, hf0s[3], m);
        }
    }
    if (tid < NB) xs[tid] = jval ? xbase[B_TOT + tid] : 0.f;   // x_1
    __syncthreads();

    // step t computes: f0_{t+1}, f1_t, b0_t, b1_{t-1}, out_{t-2}
    for (int t = 0; t < S_LEN + 2; t++) {
        const int pb = (t + 1) & 1;
        const int cb = t & 1;
        float xreg = 0.f, xbreg = 0.f;

        // ==== compute ====
        if (isF) {
            if (t < S_LEN) {
                if (jval && t + 2 < S_LEN) xreg = xbase[(t + 2) * B_TOT + j];
                const float *hvb = hf1s[pb][0];
#pragma unroll
                for (int n = 0; n < NB; n++) {
                    u64 a0 = 0, a1 = 0, a2 = 0, a3 = 0, a4 = 0, a5 = 0;
                    const ulonglong2 *hu = (const ulonglong2 *)hf0s[n];
                    const ulonglong2 *hv = (const ulonglong2 *)(hvb + n * HP);
#pragma unroll
                    for (int c = 0; c < 8; c++) {
                        ulonglong2 u = hu[c];
                        fma2(a0, w0[2 * c],     u.x);
                        fma2(a1, w0[2 * c + 1], u.y);
                        fma2(a2, w1[2 * c],     u.x);
                        fma2(a3, w1[2 * c + 1], u.y);
                        ulonglong2 v = hv[c];
                        fma2(a4, w2[2 * c],     v.x);
                        fma2(a5, w2[2 * c + 1], v.y);
                    }
                    add2(a0, a1);
                    add2(a2, a3); add2(a4, a5); add2(a2, a4);
                    float2 gv;
                    gv.x = hsum2(a0) + bias0 + wx * xs[n];          // f0_{t+1}
                    gv.y = hsum2(a2) + bias1;                       // f1_t
                    gF[n][j] = gv;
                }
            }
            // out_{t-2}: reads hf1_{t-2} (buf cb) and hb1_{t-2} (buf cb)
            if (t >= 2 && j >= 120) {
                int n = j - 120;
                if (n < NB && nb0 + n < B_TOT) {
                    const ulonglong2 *pf = (const ulonglong2 *)hf1s[cb][n];
                    const ulonglong2 *pk = (const ulonglong2 *)hb1s[cb][n];
                    const ulonglong2 *wf = (const ulonglong2 *)wls;
                    u64 acc = 0, acc2 = 0;
#pragma unroll
                    for (int c = 0; c < 8; c++) {
                        ulonglong2 u = pf[c], wu = wf[c];
                        fma2(acc,  wu.x, u.x);
                        fma2(acc2, wu.y, u.y);
                        ulonglong2 v = pk[c], wv = wf[c + 8];
                        fma2(acc,  wv.x, v.x);
                        fma2(acc2, wv.y, v.y);
                    }
                    add2(acc, acc2);
                    out[(nb0 + n) * S_LEN + (t - 2)] = hsum2(acc) + blin_s;
                }
            }
        } else {
            if (t <= S_LEN) {
                if (jval && t + 1 < S_LEN) xbreg = xbase[rb * B_TOT + j];
                const float *hvb = hf1s[pb][0];
#pragma unroll
                for (int n = 0; n < NB; n++) {
                    u64 a0 = 0, a1 = 0, a2 = 0, a3 = 0, a4 = 0, a5 = 0;
                    const ulonglong2 *hu = (const ulonglong2 *)hb0s[n];
                    const ulonglong2 *hv = (const ulonglong2 *)(hvb + n * HP);
#pragma unroll
                    for (int c = 0; c < 8; c++) {
                        ulonglong2 u = hu[c];
                        fma2(a0, w0[2 * c],     u.x);
                        fma2(a1, w0[2 * c + 1], u.y);
                        fma2(a2, w1[2 * c],     u.x);
                        fma2(a3, w1[2 * c + 1], u.y);
                        ulonglong2 v = hv[c];
                        fma2(a4, w2[2 * c],     v.x);
                        fma2(a5, w2[2 * c + 1], v.y);
                    }
                    add2(a0, a1);
                    add2(a2, a3); add2(a4, a5); add2(a2, a4);
                    float2 gv;
                    gv.x = hsum2(a0) + bias0 + wx * xbs[n];         // b0_t
                    gv.y = hsum2(a2) + bias1;                       // b1_{t-1}
                    gB[n][j] = gv;
                }
            }
            rb--; if (rb < 0) rb += S_LEN;
        }

        // per-half barrier: gates ready within this half
        if (isF) asm volatile("bar.sync 1, 128;" ::: "memory");
        else     asm volatile("bar.sync 2, 128;" ::: "memory");

        // ==== finalize ====
        if (isF) {
            if (t < S_LEN) {
                if (ng < 3) {
                    cell_pair(gF[ng],     c0_a, c1_a, hf0s[ng],     hf1s[cb][ng],     m);
                    cell_pair(gF[ng + 4], c0_b, c1_b, hf0s[ng + 4], hf1s[cb][ng + 4], m);
                } else {
                    cell_pair(gF[3], c0_a, c1_a, hf0s[3], hf1s[cb][3], m);
                }
                if (j < NB) xs[j] = xreg;                                      // x_{t+2}
            }
        } else {
            if (t >= 1 && t < S_LEN) {
                // hot path: both b0_t and b1_{t-1}
                if (ng < 3) {
                    cell_pair(gB[ng],     c0_a, c1_a, hb0s[ng],     hb1s[pb][ng],     m);
                    cell_pair(gB[ng + 4], c0_b, c1_b, hb0s[ng + 4], hb1s[pb][ng + 4], m);
                } else {
                    cell_pair(gB[3], c0_a, c1_a, hb0s[3], hb1s[pb][3], m);
                }
                if (j < NB) xbs[j] = xbreg;
            } else if (t == 0) {
                // b0 only
                if (ng < 3) {
                    cell_x(gB[ng],     c0_a, hb0s[ng],     m);
                    cell_x(gB[ng + 4], c0_b, hb0s[ng + 4], m);
                } else {
                    cell_x(gB[3], c0_a, hb0s[3], m);
                }
                if (j < NB) xbs[j] = xbreg;
            } else if (t == S_LEN) {
                // b1_{S-1} only
                if (ng < 3) {
                    cell_y(gB[ng],     c1_a, hb1s[pb][ng],     m);
                    cell_y(gB[ng + 4], c1_b, hb1s[pb][ng + 4], m);
                } else {
                    cell_y(gB[3], c1_a, hb1s[pb][3], m);
                }
            }
        }
        __syncthreads();
    }
}

extern "C" void kernel_launch(void *const *d_in, const int *in_sizes, int n_in,
                              void *d_out, int out_size)
{
    const float *x      = (const float *)d_in[0];
    const float *Wih_f0 = (const float *)d_in[1];
    const float *Whh_f0 = (const float *)d_in[2];
    const float *b_f0   = (const float *)d_in[3];
    const float *Wih_f1 = (const float *)d_in[4];
    const float *Whh_f1 = (const float *)d_in[5];
    const float *b_f1   = (const float *)d_in[6];
    const float *Wih_b0 = (const float *)d_in[7];
    const float *Whh_b0 = (const float *)d_in[8];
    const float *b_b0   = (const float *)d_in[9];
    const float *Wih_b1 = (const float *)d_in[10];
    const float *Whh_b1 = (const float *)d_in[11];
    const float *b_b1   = (const float *)d_in[12];
    const float *Wlin   = (const float *)d_in[13];
    const float *blin   = (const float *)d_in[14];
    const int   *future = (const int *)d_in[15];
    float *out = (float *)d_out;

    lstm_kernel<<<NCTA, 256>>>(x,
                               Wih_f0, Whh_f0, b_f0,
                               Wih_f1, Whh_f1, b_f1,
                               Wih_b0, Whh_b0, b_b0,
                               Wih_b1, Whh_b1, b_b1,
                               Wlin, blin, future, out);
}